// round 1
// baseline (speedup 1.0000x reference)
#include <cuda_runtime.h>

#define B_ 4
#define M_ 4096
#define D_ 64
#define W_ 128

__global__ __launch_bounds__(128) void sparse_attn_kernel(
    const float* __restrict__ q, const float* __restrict__ k,
    const float* __restrict__ v, const int* __restrict__ cidx,
    float* __restrict__ out)
{
    const int m   = blockIdx.x;
    const int b   = blockIdx.y;
    const int tid = threadIdx.x;   // 0..127

    __shared__ float  sq[D_];
    __shared__ int    sidx[W_];
    __shared__ float  sw[W_];
    __shared__ float  sred[4];
    __shared__ float2 spart[3][32];

    // Stage q row and the 128 gather indices for this m.
    if (tid < D_) sq[tid] = q[((size_t)b * M_ + m) * D_ + tid];
    sidx[tid] = cidx[(size_t)m * W_ + tid];
    __syncthreads();

    // ---- Phase 1: logits. Thread w does the full 64-dim dot for column w.
    const float4* krow = reinterpret_cast<const float4*>(
        k + ((size_t)b * M_ + sidx[tid]) * D_);
    const float4* q4 = reinterpret_cast<const float4*>(sq);
    float acc = 0.f;
    #pragma unroll
    for (int i = 0; i < D_ / 4; ++i) {
        float4 kk = __ldg(&krow[i]);
        float4 qq = q4[i];
        acc = fmaf(kk.x, qq.x, acc);
        acc = fmaf(kk.y, qq.y, acc);
        acc = fmaf(kk.z, qq.z, acc);
        acc = fmaf(kk.w, qq.w, acc);
    }

    // ---- Softmax over the 128 logits (block-wide, 4 warps).
    float mx = acc;
    #pragma unroll
    for (int o = 16; o; o >>= 1)
        mx = fmaxf(mx, __shfl_xor_sync(0xffffffffu, mx, o));
    if ((tid & 31) == 0) sred[tid >> 5] = mx;
    __syncthreads();
    mx = fmaxf(fmaxf(sred[0], sred[1]), fmaxf(sred[2], sred[3]));

    float e = __expf(acc - mx);
    sw[tid] = e;
    float sm = e;
    #pragma unroll
    for (int o = 16; o; o >>= 1)
        sm += __shfl_xor_sync(0xffffffffu, sm, o);
    __syncthreads();                       // everyone done reading sred (max)
    if ((tid & 31) == 0) sred[tid >> 5] = sm;
    __syncthreads();
    const float inv_tot = 1.f / (sred[0] + sred[1] + sred[2] + sred[3]);

    // ---- Phase 2: out[d] = sum_w weight[w] * v[idx[w]][d].
    // Remap: d2 = float2 lane over D (32 lanes), g strides w by 4.
    // A warp (fixed g, fixed w) loads 32 consecutive float2 => coalesced 256B.
    const int d2 = tid & 31;
    const int g  = tid >> 5;
    float2 oacc = make_float2(0.f, 0.f);
    #pragma unroll 8
    for (int w = g; w < W_; w += 4) {
        const float wt = sw[w];
        const float2* vrow = reinterpret_cast<const float2*>(
            v + ((size_t)b * M_ + sidx[w]) * D_);
        float2 vv = __ldg(&vrow[d2]);
        oacc.x = fmaf(wt, vv.x, oacc.x);
        oacc.y = fmaf(wt, vv.y, oacc.y);
    }
    if (g > 0) spart[g - 1][d2] = oacc;
    __syncthreads();
    if (g == 0) {
        float2 r = oacc;
        #pragma unroll
        for (int j = 0; j < 3; ++j) {
            r.x += spart[j][d2].x;
            r.y += spart[j][d2].y;
        }
        float2* orow = reinterpret_cast<float2*>(out + ((size_t)b * M_ + m) * D_);
        orow[d2] = make_float2(r.x * inv_tot, r.y * inv_tot);
    }
}

extern "C" void kernel_launch(void* const* d_in, const int* in_sizes, int n_in,
                              void* d_out, int out_size)
{
    const float* q  = (const float*)d_in[0];
    const float* k  = (const float*)d_in[1];
    const float* v  = (const float*)d_in[2];
    const int*   ci = (const int*)d_in[3];
    float* out = (float*)d_out;

    dim3 grid(M_, B_);
    sparse_attn_kernel<<<grid, 128>>>(q, k, v, ci, out);
}

// round 2
// speedup vs baseline: 1.9400x; 1.9400x over previous
#include <cuda_runtime.h>

#define B_ 4
#define M_ 4096
#define D_ 64
#define W_ 128

__global__ __launch_bounds__(128) void sparse_attn_kernel(
    const float* __restrict__ q, const float* __restrict__ k,
    const float* __restrict__ v, const int* __restrict__ cidx,
    float* __restrict__ out)
{
    const int m    = blockIdx.x;
    const int b    = blockIdx.y;
    const int tid  = threadIdx.x;    // 0..127
    const int lane = tid & 31;
    const int wid  = tid >> 5;       // 4 warps
    const int hl   = lane & 15;      // half-lane: float4 slot within a row
    const int sub  = lane >> 4;      // which row of the pair (0/1)

    __shared__ int    sidx[W_];
    __shared__ float  sw[W_];
    __shared__ float  sred[4];
    __shared__ float2 spart[3][32];

    // Stage the 128 gather indices (coalesced, one load per thread).
    sidx[tid] = cidx[(size_t)m * W_ + tid];

    // q slice in registers: lane holds q[4*hl .. 4*hl+3].
    const float4* q4 = reinterpret_cast<const float4*>(q + ((size_t)b * M_ + m) * D_);
    const float4  qq = __ldg(&q4[hl]);
    __syncthreads();

    // ---- Phase 1: logits, fully coalesced gathers.
    // Warp 'wid' owns columns [wid*32, wid*32+32), two per iteration:
    // lanes 0-15 cover row for column 2c (one float4 each = full 256B row),
    // lanes 16-31 cover row for column 2c+1.
    const float* kb = k + (size_t)b * M_ * D_;
    #pragma unroll 4
    for (int it = 0; it < 16; ++it) {
        const int col = wid * 32 + it * 2 + sub;
        const int row = sidx[col];
        const float4 kk = __ldg(reinterpret_cast<const float4*>(kb + (size_t)row * D_) + hl);
        float p = kk.x * qq.x;
        p = fmaf(kk.y, qq.y, p);
        p = fmaf(kk.z, qq.z, p);
        p = fmaf(kk.w, qq.w, p);
        // reduce across the 16 half-lanes (halves don't mix at offsets < 16)
        p += __shfl_xor_sync(0xffffffffu, p, 8);
        p += __shfl_xor_sync(0xffffffffu, p, 4);
        p += __shfl_xor_sync(0xffffffffu, p, 2);
        p += __shfl_xor_sync(0xffffffffu, p, 1);
        if (hl == 0) sw[col] = p;
    }
    __syncthreads();

    // ---- Softmax over 128 logits (block-wide, 4 warps). Thread tid owns logit tid.
    const float acc = sw[tid];
    float mx = acc;
    #pragma unroll
    for (int o = 16; o; o >>= 1)
        mx = fmaxf(mx, __shfl_xor_sync(0xffffffffu, mx, o));
    if (lane == 0) sred[wid] = mx;
    __syncthreads();
    mx = fmaxf(fmaxf(sred[0], sred[1]), fmaxf(sred[2], sred[3]));

    const float e = __expf(acc - mx);
    sw[tid] = e;                      // only thread tid read sw[tid]; safe overwrite
    float sm = e;
    #pragma unroll
    for (int o = 16; o; o >>= 1)
        sm += __shfl_xor_sync(0xffffffffu, sm, o);
    __syncthreads();                  // everyone done reading sred (max)
    if (lane == 0) sred[wid] = sm;
    __syncthreads();
    const float inv_tot = 1.f / (sred[0] + sred[1] + sred[2] + sred[3]);

    // ---- Phase 2: out[d] = sum_w weight[w] * v[idx[w]][d]; coalesced float2.
    const int d2 = lane;             // float2 lane over D (32 lanes)
    const int g  = wid;              // warp strides w by 4
    float2 oacc = make_float2(0.f, 0.f);
    #pragma unroll 8
    for (int w = g; w < W_; w += 4) {
        const float wt = sw[w];
        const float2* vrow = reinterpret_cast<const float2*>(
            v + ((size_t)b * M_ + sidx[w]) * D_);
        const float2 vv = __ldg(&vrow[d2]);
        oacc.x = fmaf(wt, vv.x, oacc.x);
        oacc.y = fmaf(wt, vv.y, oacc.y);
    }
    if (g > 0) spart[g - 1][d2] = oacc;
    __syncthreads();
    if (g == 0) {
        float2 r = oacc;
        #pragma unroll
        for (int j = 0; j < 3; ++j) {
            r.x += spart[j][d2].x;
            r.y += spart[j][d2].y;
        }
        float2* orow = reinterpret_cast<float2*>(out + ((size_t)b * M_ + m) * D_);
        orow[d2] = make_float2(r.x * inv_tot, r.y * inv_tot);
    }
}

extern "C" void kernel_launch(void* const* d_in, const int* in_sizes, int n_in,
                              void* d_out, int out_size)
{
    const float* q  = (const float*)d_in[0];
    const float* k  = (const float*)d_in[1];
    const float* v  = (const float*)d_in[2];
    const int*   ci = (const int*)d_in[3];
    float* out = (float*)d_out;

    dim3 grid(M_, B_);
    sparse_attn_kernel<<<grid, 128>>>(q, k, v, ci, out);
}

// round 4
// speedup vs baseline: 2.8014x; 1.4440x over previous
#include <cuda_runtime.h>
#include <cuda_fp16.h>

#define B_ 4
#define M_ 4096
#define D_ 64
#define W_ 128

// v converted to fp16 once per launch (inside the graph): [b][m][d/2] half2
__device__ __half2 g_vh[B_ * M_ * D_ / 2];

__global__ __launch_bounds__(256) void convert_v_kernel(const float* __restrict__ v)
{
    const int i = blockIdx.x * blockDim.x + threadIdx.x;   // float4 index
    const int n4 = B_ * M_ * D_ / 4;
    if (i < n4) {
        const float4 f = reinterpret_cast<const float4*>(v)[i];
        g_vh[2 * i]     = __floats2half2_rn(f.x, f.y);
        g_vh[2 * i + 1] = __floats2half2_rn(f.z, f.w);
    }
}

__global__ __launch_bounds__(128) void sparse_attn_kernel(
    const float* __restrict__ q, const float* __restrict__ k,
    const int* __restrict__ cidx, float* __restrict__ out)
{
    const int m    = blockIdx.x;
    const int b    = blockIdx.y;
    const int tid  = threadIdx.x;    // 0..127
    const int lane = tid & 31;
    const int wid  = tid >> 5;       // 4 warps; warp owns columns [32*wid, 32*wid+32)
    const int c8   = lane & 7;       // position within a k-row (8 lanes per row)
    const int r4   = lane >> 3;      // which of 4 rows in a gather group (bits {4,3})

    __shared__ int   sidx[W_];
    __shared__ __align__(16) uint2 swp[W_];  // packed {exp-weight bits, gather row}
    __shared__ float sredm[4], sreds[4];
    __shared__ float2 spart[3][32];

    // Stage the 128 gather indices (coalesced).
    sidx[tid] = cidx[(size_t)m * W_ + tid];

    // q slice in registers: lane covers float4 #c8 and #(c8+8) of the q row.
    const float4* q4 = reinterpret_cast<const float4*>(q + ((size_t)b * M_ + m) * D_);
    const float4 qa = __ldg(&q4[c8]);
    const float4 qb = __ldg(&q4[c8 + 8]);
    __syncthreads();

    // ---- Phase 1: logits. 4 rows per LDG pair (8 lanes/row), 2 wf per row.
    const float* kb = k + (size_t)b * M_ * D_;
    float L[4];   // L[Bt] at this lane = logit of col = 32*wid + 8*Bt + 4*b2 + r4

    #pragma unroll
    for (int Bt = 0; Bt < 4; ++Bt) {
        float p[2];
        #pragma unroll
        for (int s = 0; s < 2; ++s) {
            const int row = sidx[32 * wid + 4 * (2 * Bt + s) + r4];
            const float4* kr = reinterpret_cast<const float4*>(kb + (size_t)row * D_);
            const float4 ka = __ldg(&kr[c8]);
            const float4 kc = __ldg(&kr[c8 + 8]);
            float t = ka.x * qa.x;
            t = fmaf(ka.y, qa.y, t);
            t = fmaf(ka.z, qa.z, t);
            t = fmaf(ka.w, qa.w, t);
            t = fmaf(kc.x, qb.x, t);
            t = fmaf(kc.y, qb.y, t);
            t = fmaf(kc.z, qb.z, t);
            t = fmaf(kc.w, qb.w, t);
            p[s] = t;
        }
        // reduce over lane bits {2,1,0} with a select-merge tree: 4 SHFL / 8 cols
        p[0] += __shfl_xor_sync(0xffffffffu, p[0], 4);
        p[1] += __shfl_xor_sync(0xffffffffu, p[1], 4);
        float t = (lane & 4) ? p[1] : p[0];
        t += __shfl_xor_sync(0xffffffffu, t, 2);
        t += __shfl_xor_sync(0xffffffffu, t, 1);
        L[Bt] = t;   // col = 32*wid + 8*Bt + 4*((lane>>2)&1) + (lane>>3)
    }

    // ---- Softmax (logits live in registers; reduce over lane bits {4,3,2};
    // bits {1,0} are duplicates and excluded from the sum).
    float mx = fmaxf(fmaxf(L[0], L[1]), fmaxf(L[2], L[3]));
    mx = fmaxf(mx, __shfl_xor_sync(0xffffffffu, mx, 16));
    mx = fmaxf(mx, __shfl_xor_sync(0xffffffffu, mx, 8));
    mx = fmaxf(mx, __shfl_xor_sync(0xffffffffu, mx, 4));
    if (lane == 0) sredm[wid] = mx;
    __syncthreads();
    const float bm = fmaxf(fmaxf(sredm[0], sredm[1]), fmaxf(sredm[2], sredm[3]));

    float e[4];
    #pragma unroll
    for (int Bt = 0; Bt < 4; ++Bt) e[Bt] = __expf(L[Bt] - bm);
    float sm = (e[0] + e[1]) + (e[2] + e[3]);
    sm += __shfl_xor_sync(0xffffffffu, sm, 16);
    sm += __shfl_xor_sync(0xffffffffu, sm, 8);
    sm += __shfl_xor_sync(0xffffffffu, sm, 4);
    if (lane == 0) sreds[wid] = sm;

    // Pack {e, idx} for this warp's 32 columns. Lanes with (lane&3)==0 hold 8
    // distinct (b2, r4) combos; col matches the phase-1 formula exactly.
    if ((lane & 3) == 0) {
        const int cbase = 32 * wid + 4 * ((lane >> 2) & 1) + (lane >> 3);
        #pragma unroll
        for (int Bt = 0; Bt < 4; ++Bt) {
            const int col = cbase + 8 * Bt;
            swp[col] = make_uint2(__float_as_uint(e[Bt]), (unsigned)sidx[col]);
        }
    }
    __syncthreads();
    const float inv_tot = 1.f / (sreds[0] + sreds[1] + sreds[2] + sreds[3]);

    // ---- Phase 2: out accumulation over this warp's 32 columns, v in fp16.
    // lane = half2 index over D (32 lanes x 4B = one 128B row per LDG = 1 wf).
    const __half2* vb = g_vh + (size_t)b * M_ * (D_ / 2);
    float2 oacc = make_float2(0.f, 0.f);
    #pragma unroll
    for (int j = 0; j < 32; j += 2) {
        const uint4 pk = *reinterpret_cast<const uint4*>(&swp[32 * wid + j]);
        const float w0 = __uint_as_float(pk.x);
        const float w1 = __uint_as_float(pk.z);
        const __half2 h0 = __ldg(&vb[(size_t)pk.y * (D_ / 2) + lane]);
        const __half2 h1 = __ldg(&vb[(size_t)pk.w * (D_ / 2) + lane]);
        const float2 f0 = __half22float2(h0);
        const float2 f1 = __half22float2(h1);
        oacc.x = fmaf(w0, f0.x, oacc.x);
        oacc.y = fmaf(w0, f0.y, oacc.y);
        oacc.x = fmaf(w1, f1.x, oacc.x);
        oacc.y = fmaf(w1, f1.y, oacc.y);
    }

    if (wid > 0) spart[wid - 1][lane] = oacc;
    __syncthreads();
    if (wid == 0) {
        float2 r = oacc;
        #pragma unroll
        for (int j = 0; j < 3; ++j) {
            r.x += spart[j][lane].x;
            r.y += spart[j][lane].y;
        }
        float2* orow = reinterpret_cast<float2*>(out + ((size_t)b * M_ + m) * D_);
        orow[lane] = make_float2(r.x * inv_tot, r.y * inv_tot);
    }
}

extern "C" void kernel_launch(void* const* d_in, const int* in_sizes, int n_in,
                              void* d_out, int out_size)
{
    const float* q  = (const float*)d_in[0];
    const float* k  = (const float*)d_in[1];
    const float* v  = (const float*)d_in[2];
    const int*   ci = (const int*)d_in[3];
    float* out = (float*)d_out;

    convert_v_kernel<<<(B_ * M_ * D_ / 4 + 255) / 256, 256>>>(v);
    dim3 grid(M_, B_);
    sparse_attn_kernel<<<grid, 128>>>(q, k, ci, out);
}